// round 2
// baseline (speedup 1.0000x reference)
#include <cuda_runtime.h>
#include <cstddef>

// Problem dims (fixed by the dataset)
#define M_DIM 8192
#define N_DIM 1536
#define K_DIM 512
#define H_DIM 512

// Scratch for gate pre-activations (quantized to 2^-14 grid), 50MB each.
__device__ float g_gi[(size_t)M_DIM * N_DIM];
__device__ float g_gh[(size_t)M_DIM * N_DIM];

// ---------------------------------------------------------------------------
// Quantization helpers — replicate JAX fp32 semantics exactly:
// each multiply and add is separately rounded (no FMA contraction).
// ---------------------------------------------------------------------------
__device__ __forceinline__ float qround(float x, float s, float inv) {
    return __fmul_rn(floorf(__fadd_rn(__fmul_rn(x, s), 0.5f)), inv);
}

#define Q27F   134217728.0f
#define IQ27F  7.450580596923828125e-9f    // 2^-27
#define Q31F   2147483648.0f
#define IQ16F  1.52587890625e-5f           // 2^-16
#define S15F   32768.0f
#define I15F   3.0517578125e-5f            // 2^-15
#define S14F   16384.0f
#define I14F   6.103515625e-5f             // 2^-14

__device__ __forceinline__ float qsig(float x) {
    float t = floorf(__fadd_rn(__fmul_rn(x, Q27F), 0.5f));
    t = fminf(fmaxf(t, -2147483648.0f), 2147483648.0f);  // fp32(2^31-1) == 2^31
    float xr = __fmul_rn(t, IQ27F);
    float s  = 1.0f / (1.0f + expf(-xr));
    float q31 = floorf(__fadd_rn(__fmul_rn(s, Q31F), 0.5f));
    float q15 = floorf(__fadd_rn(__fmul_rn(q31, IQ16F), 0.5f));
    return __fmul_rn(q15, I15F);
}

__device__ __forceinline__ float qtanhf_(float x) {
    float t = floorf(__fadd_rn(__fmul_rn(x, Q27F), 0.5f));
    t = fminf(fmaxf(t, -2147483648.0f), 2147483648.0f);
    float xr = __fmul_rn(t, IQ27F);
    float s  = tanhf(xr);
    float q31 = floorf(__fadd_rn(__fmul_rn(s, Q31F), 0.5f));
    float q15 = floorf(__fadd_rn(__fmul_rn(q31, IQ16F), 0.5f));
    return __fmul_rn(q15, I15F);
}

// ---------------------------------------------------------------------------
// GEMM: C[m,n] = quant14( sum_k A[m,k]*W[n,k] + bias[n] )
// A:[M,K] row-major, W:[N,K] row-major (so both K-contiguous).
// 128x128 tile, BK=16, 256 threads, 8x8 per thread.
// ---------------------------------------------------------------------------
#define BM 128
#define BN 128
#define BK 16
#define SPAD 4   // row stride 132 floats = 528B (multiple of 16B -> float4 ok)

__global__ __launch_bounds__(256)
void gemm_bias_q14(const float* __restrict__ A,
                   const float* __restrict__ W,
                   const float* __restrict__ bias,
                   int which)   // 0 -> g_gi, 1 -> g_gh
{
    __shared__ float As[BK][BM + SPAD];
    __shared__ float Bs[BK][BN + SPAD];

    float* __restrict__ C = which ? g_gh : g_gi;

    const int tid = threadIdx.x;
    const int m0 = blockIdx.y * BM;
    const int n0 = blockIdx.x * BN;

    // loaders: each thread loads 2 float4 from A and 2 from W per K-tile
    const int lr = tid >> 2;          // 0..63 (row within half-tile)
    const int lk = (tid & 3) << 2;    // 0,4,8,12 (k offset)

    // compute mapping: 16x16 threads, 8x8 each
    const int tx = tid & 15;
    const int ty = tid >> 4;

    float acc[8][8];
    #pragma unroll
    for (int i = 0; i < 8; i++)
        #pragma unroll
        for (int j = 0; j < 8; j++) acc[i][j] = 0.0f;

    const float* Ab = A + (size_t)m0 * K_DIM;
    const float* Wb = W + (size_t)n0 * K_DIM;

    for (int k0 = 0; k0 < K_DIM; k0 += BK) {
        #pragma unroll
        for (int s = 0; s < 2; s++) {
            int row = lr + s * 64;
            float4 va = *reinterpret_cast<const float4*>(Ab + (size_t)row * K_DIM + k0 + lk);
            As[lk + 0][row] = va.x;
            As[lk + 1][row] = va.y;
            As[lk + 2][row] = va.z;
            As[lk + 3][row] = va.w;
            float4 vb = *reinterpret_cast<const float4*>(Wb + (size_t)row * K_DIM + k0 + lk);
            Bs[lk + 0][row] = vb.x;
            Bs[lk + 1][row] = vb.y;
            Bs[lk + 2][row] = vb.z;
            Bs[lk + 3][row] = vb.w;
        }
        __syncthreads();

        #pragma unroll
        for (int kk = 0; kk < BK; kk++) {
            float4 a01 = *reinterpret_cast<const float4*>(&As[kk][ty * 8]);
            float4 a23 = *reinterpret_cast<const float4*>(&As[kk][ty * 8 + 4]);
            float4 b01 = *reinterpret_cast<const float4*>(&Bs[kk][tx * 8]);
            float4 b23 = *reinterpret_cast<const float4*>(&Bs[kk][tx * 8 + 4]);
            float a[8] = {a01.x, a01.y, a01.z, a01.w, a23.x, a23.y, a23.z, a23.w};
            float b[8] = {b01.x, b01.y, b01.z, b01.w, b23.x, b23.y, b23.z, b23.w};
            #pragma unroll
            for (int i = 0; i < 8; i++)
                #pragma unroll
                for (int j = 0; j < 8; j++)
                    acc[i][j] += a[i] * b[j];   // FMA contraction fine here
        }
        __syncthreads();
    }

    // epilogue: +bias, quantize to 2^-14 grid, store
    float bv[8];
    #pragma unroll
    for (int j = 0; j < 8; j++) bv[j] = bias[n0 + tx * 8 + j];

    #pragma unroll
    for (int i = 0; i < 8; i++) {
        int m = m0 + ty * 8 + i;
        float* Crow = C + (size_t)m * N_DIM + n0 + tx * 8;
        float4 o0, o1;
        o0.x = qround(acc[i][0] + bv[0], S14F, I14F);
        o0.y = qround(acc[i][1] + bv[1], S14F, I14F);
        o0.z = qround(acc[i][2] + bv[2], S14F, I14F);
        o0.w = qround(acc[i][3] + bv[3], S14F, I14F);
        o1.x = qround(acc[i][4] + bv[4], S14F, I14F);
        o1.y = qround(acc[i][5] + bv[5], S14F, I14F);
        o1.z = qround(acc[i][6] + bv[6], S14F, I14F);
        o1.w = qround(acc[i][7] + bv[7], S14F, I14F);
        *reinterpret_cast<float4*>(Crow)     = o0;
        *reinterpret_cast<float4*>(Crow + 4) = o1;
    }
}

// ---------------------------------------------------------------------------
// Fused gate epilogue over [B, H], float4-vectorized.
// ---------------------------------------------------------------------------
__global__ __launch_bounds__(256)
void qgru_epilogue(const float* __restrict__ hidden, float* __restrict__ out)
{
    int idx = blockIdx.x * blockDim.x + threadIdx.x;
    if (idx >= (M_DIM * H_DIM) / 4) return;
    int b = idx >> 7;            // /128  (H/4 = 128 float4 per row)
    int h = (idx & 127) << 2;

    const float* gib = g_gi + (size_t)b * N_DIM;
    const float* ghb = g_gh + (size_t)b * N_DIM;

    float4 ir = *reinterpret_cast<const float4*>(gib + h);
    float4 ii = *reinterpret_cast<const float4*>(gib + h + H_DIM);
    float4 in_ = *reinterpret_cast<const float4*>(gib + h + 2 * H_DIM);
    float4 hr = *reinterpret_cast<const float4*>(ghb + h);
    float4 hi = *reinterpret_cast<const float4*>(ghb + h + H_DIM);
    float4 hn = *reinterpret_cast<const float4*>(ghb + h + 2 * H_DIM);
    float4 hd = *reinterpret_cast<const float4*>(hidden + (size_t)b * H_DIM + h);

    float irA[4] = {ir.x, ir.y, ir.z, ir.w};
    float iiA[4] = {ii.x, ii.y, ii.z, ii.w};
    float inA[4] = {in_.x, in_.y, in_.z, in_.w};
    float hrA[4] = {hr.x, hr.y, hr.z, hr.w};
    float hiA[4] = {hi.x, hi.y, hi.z, hi.w};
    float hnA[4] = {hn.x, hn.y, hn.z, hn.w};
    float hdA[4] = {hd.x, hd.y, hd.z, hd.w};
    float res[4];

    #pragma unroll
    for (int l = 0; l < 4; l++) {
        float rg  = qsig(__fadd_rn(irA[l], hrA[l]));
        float ig  = qsig(__fadd_rn(iiA[l], hiA[l]));
        float hnq = qround(hnA[l], Q27F, IQ27F);
        float rh  = qround(__fmul_rn(rg, hnq), S15F, I15F);
        float ng  = qtanhf_(__fadd_rn(rh, inA[l]));
        float nh  = qround(hdA[l], S15F, I15F);
        res[l] = __fadd_rn(ng, __fmul_rn(ig, __fsub_rn(nh, ng)));
    }

    float4 o = {res[0], res[1], res[2], res[3]};
    *reinterpret_cast<float4*>(out + (size_t)b * H_DIM + h) = o;
}

// ---------------------------------------------------------------------------
extern "C" void kernel_launch(void* const* d_in, const int* in_sizes, int n_in,
                              void* d_out, int out_size)
{
    const float* x   = (const float*)d_in[0];
    const float* h   = (const float*)d_in[1];
    const float* wih = (const float*)d_in[2];
    const float* whh = (const float*)d_in[3];
    const float* bih = (const float*)d_in[4];
    const float* bhh = (const float*)d_in[5];
    float* out = (float*)d_out;

    dim3 grid(N_DIM / BN, M_DIM / BM);   // (12, 64)
    gemm_bias_q14<<<grid, 256>>>(x, wih, bih, 0);
    gemm_bias_q14<<<grid, 256>>>(h, whh, bhh, 1);

    int total = (M_DIM * H_DIM) / 4;
    qgru_epilogue<<<(total + 255) / 256, 256>>>(h, out);
}

// round 6
// speedup vs baseline: 1.8887x; 1.8887x over previous
#include <cuda_runtime.h>
#include <cuda_bf16.h>
#include <cstdint>
#include <cstddef>

// Problem dims (fixed by the dataset)
#define M_DIM 8192
#define N_DIM 1536
#define K_DIM 512
#define H_DIM 512
#define KP    (3 * K_DIM)     // packed K' = 1536

// ---------------------------------------------------------------------------
// Device-global scratch (no cudaMalloc allowed)
// ---------------------------------------------------------------------------
__device__ float g_gi[(size_t)M_DIM * N_DIM];
__device__ float g_gh[(size_t)M_DIM * N_DIM];

// Packed split operands: A' = [hi | hi | lo], B' = [hi | lo | hi]
__device__ __nv_bfloat16 g_xp[(size_t)M_DIM * KP];
__device__ __nv_bfloat16 g_hp[(size_t)M_DIM * KP];
__device__ __nv_bfloat16 g_wip[(size_t)N_DIM * KP];
__device__ __nv_bfloat16 g_whp[(size_t)N_DIM * KP];

// ---------------------------------------------------------------------------
// Quantization helpers (exact fp32 semantics, no FMA contraction)
// ---------------------------------------------------------------------------
#define Q27F   134217728.0f
#define IQ27F  7.450580596923828125e-9f    // 2^-27
#define Q31F   2147483648.0f
#define IQ16F  1.52587890625e-5f           // 2^-16
#define S15F   32768.0f
#define I15F   3.0517578125e-5f            // 2^-15
#define S14F   16384.0f
#define I14F   6.103515625e-5f             // 2^-14

__device__ __forceinline__ float qround(float x, float s, float inv) {
    return __fmul_rn(floorf(__fadd_rn(__fmul_rn(x, s), 0.5f)), inv);
}

__device__ __forceinline__ float qsig(float x) {
    float t = floorf(__fadd_rn(__fmul_rn(x, Q27F), 0.5f));
    t = fminf(fmaxf(t, -2147483648.0f), 2147483648.0f);
    float xr = __fmul_rn(t, IQ27F);
    float s  = 1.0f / (1.0f + expf(-xr));
    float q31 = floorf(__fadd_rn(__fmul_rn(s, Q31F), 0.5f));
    float q15 = floorf(__fadd_rn(__fmul_rn(q31, IQ16F), 0.5f));
    return __fmul_rn(q15, I15F);
}

__device__ __forceinline__ float qtanhf_(float x) {
    float t = floorf(__fadd_rn(__fmul_rn(x, Q27F), 0.5f));
    t = fminf(fmaxf(t, -2147483648.0f), 2147483648.0f);
    float xr = __fmul_rn(t, IQ27F);
    float s  = tanhf(xr);
    float q31 = floorf(__fadd_rn(__fmul_rn(s, Q31F), 0.5f));
    float q15 = floorf(__fadd_rn(__fmul_rn(q31, IQ16F), 0.5f));
    return __fmul_rn(q15, I15F);
}

// ---------------------------------------------------------------------------
// PTX helpers (baseline sm_103-safe: mma.sync / ldmatrix / cp.async only)
// ---------------------------------------------------------------------------
__device__ __forceinline__ uint32_t smem_u32(const void* p) {
    uint32_t a;
    asm("{ .reg .u64 t; cvta.to.shared.u64 t, %1; cvt.u32.u64 %0, t; }" : "=r"(a) : "l"(p));
    return a;
}

__device__ __forceinline__ void cp16(uint32_t dst, const void* src) {
    asm volatile("cp.async.cg.shared.global [%0], [%1], 16;" :: "r"(dst), "l"(src) : "memory");
}

__device__ __forceinline__ void ldmatrix_x4(uint32_t& r0, uint32_t& r1,
                                            uint32_t& r2, uint32_t& r3,
                                            uint32_t addr) {
    asm volatile("ldmatrix.sync.aligned.m8n8.x4.shared.b16 {%0,%1,%2,%3}, [%4];"
                 : "=r"(r0), "=r"(r1), "=r"(r2), "=r"(r3) : "r"(addr));
}

__device__ __forceinline__ void mma_bf16(float& d0, float& d1, float& d2, float& d3,
                                         uint32_t a0, uint32_t a1, uint32_t a2, uint32_t a3,
                                         uint32_t b0, uint32_t b1) {
    asm volatile(
        "mma.sync.aligned.m16n8k16.row.col.f32.bf16.bf16.f32 "
        "{%0,%1,%2,%3}, {%4,%5,%6,%7}, {%8,%9}, {%0,%1,%2,%3};"
        : "+f"(d0), "+f"(d1), "+f"(d2), "+f"(d3)
        : "r"(a0), "r"(a1), "r"(a2), "r"(a3), "r"(b0), "r"(b1));
}

// ---------------------------------------------------------------------------
// fp32 -> packed bf16 hi/lo split.
// mode 0 (activations A'): [hi | hi | lo]
// mode 1 (weights     B'): [hi | lo | hi]
// ---------------------------------------------------------------------------
__global__ __launch_bounds__(256)
void split_pack(const float* __restrict__ src, __nv_bfloat16* __restrict__ dst,
                int rows, int mode)
{
    int i = blockIdx.x * blockDim.x + threadIdx.x;
    if (i >= rows * K_DIM) return;
    int m = i >> 9;            // / K_DIM
    int k = i & 511;
    float v = src[i];
    __nv_bfloat16 hi = __float2bfloat16_rn(v);
    __nv_bfloat16 lo = __float2bfloat16_rn(v - __bfloat162float(hi));
    __nv_bfloat16* d = dst + (size_t)m * KP + k;
    d[0] = hi;
    d[K_DIM]     = mode ? lo : hi;
    d[2 * K_DIM] = mode ? hi : lo;
}

// ---------------------------------------------------------------------------
// GEMM via mma.sync (bf16, fp32 accum):
//   C[m,n] = q14( sum_{k'} A'[m,k'] * B'[n,k'] + bias[n] )
// Tile 128x128, BK=32, 256 threads (8 warps, each 32x64), 2-stage cp.async.
// grid = (12, 64, 2); z selects (x,Wih,gi,bih) vs (h,Whh,gh,bhh).
// ---------------------------------------------------------------------------
#define TILE_M 128
#define TILE_N 128
#define BK 32
#define NCH (KP / BK)          // 48
#define ROWSTRIDE 40           // bf16 elements per smem row (64B data + 16B pad)

__global__ __launch_bounds__(256)
void gemm_mma(const float* __restrict__ bias_i, const float* __restrict__ bias_h)
{
    __shared__ __align__(16) __nv_bfloat16 As[2][TILE_M][ROWSTRIDE];
    __shared__ __align__(16) __nv_bfloat16 Bs[2][TILE_N][ROWSTRIDE];
    __shared__ float sb_bias[TILE_N];

    const int tid = threadIdx.x;
    const int wid = tid >> 5, lane = tid & 31;
    const int n0 = blockIdx.x * TILE_N;
    const int m0 = blockIdx.y * TILE_M;
    const int z  = blockIdx.z;

    const __nv_bfloat16* __restrict__ A = z ? g_hp  : g_xp;
    const __nv_bfloat16* __restrict__ B = z ? g_whp : g_wip;
    const float* __restrict__ bias = z ? bias_h : bias_i;
    float* __restrict__ C = z ? g_gh : g_gi;

    if (tid < TILE_N) sb_bias[tid] = bias[n0 + tid];

    // loader mapping: 2 x 16B per operand per thread per chunk
    const int lrow0 = tid >> 2;          // for op0: rows 0..63
    const int lseg  = tid & 3;

    // warp tile: 4x2 grid of warps -> each warp 32 (m) x 64 (n)
    const int wm = (wid & 3) * 32;
    const int wn = (wid >> 2) * 64;
    const int g  = lane >> 2;            // group id 0..7
    const int tq = lane & 3;

    float d[2][8][4];
    #pragma unroll
    for (int a = 0; a < 2; a++)
        #pragma unroll
        for (int b = 0; b < 8; b++)
            #pragma unroll
            for (int c = 0; c < 4; c++) d[a][b][c] = 0.0f;

    // precomputed ldmatrix smem row/seg indices for this lane
    const int lm_row = (lane & 15);              // A: row within m16 tile
    const int lm_hi  = (lane >> 4) & 1;          // A: k-half select
    const int lb_row = ((lane >> 4) & 1) * 8 + (lane & 7);   // B: row within n16
    const int lb_seg = (lane >> 3) & 1;          // B: k-half select

    // prologue: load chunk 0 into stage 0
    {
        const __nv_bfloat16* Ag = A + (size_t)m0 * KP;
        const __nv_bfloat16* Bg = B + (size_t)n0 * KP;
        #pragma unroll
        for (int o = 0; o < 2; o++) {
            int lin = tid + o * 256;
            int row = lin >> 2, seg = lin & 3;
            cp16(smem_u32(&As[0][row][seg * 8]), Ag + (size_t)row * KP + seg * 8);
            cp16(smem_u32(&Bs[0][row][seg * 8]), Bg + (size_t)row * KP + seg * 8);
        }
        asm volatile("cp.async.commit_group;" ::: "memory");
    }

    for (int c = 0; c < NCH; c++) {
        const int s = c & 1;

        if (c + 1 < NCH) {
            const int kk = (c + 1) * BK;
            const __nv_bfloat16* Ag = A + (size_t)m0 * KP + kk;
            const __nv_bfloat16* Bg = B + (size_t)n0 * KP + kk;
            #pragma unroll
            for (int o = 0; o < 2; o++) {
                int lin = tid + o * 256;
                int row = lin >> 2, seg = lin & 3;
                cp16(smem_u32(&As[s ^ 1][row][seg * 8]), Ag + (size_t)row * KP + seg * 8);
                cp16(smem_u32(&Bs[s ^ 1][row][seg * 8]), Bg + (size_t)row * KP + seg * 8);
            }
            asm volatile("cp.async.commit_group;" ::: "memory");
            asm volatile("cp.async.wait_group 1;" ::: "memory");
        } else {
            asm volatile("cp.async.wait_group 0;" ::: "memory");
        }
        __syncthreads();

        #pragma unroll
        for (int ks = 0; ks < 2; ks++) {
            // A fragments: 2 m16 tiles
            uint32_t aF[2][4];
            #pragma unroll
            for (int mt = 0; mt < 2; mt++) {
                uint32_t addr = smem_u32(
                    &As[s][wm + mt * 16 + lm_row][ks * 16 + lm_hi * 8]);
                ldmatrix_x4(aF[mt][0], aF[mt][1], aF[mt][2], aF[mt][3], addr);
            }
            // B fragments: 8 n8 tiles (loaded as 4 x (n16 x k16))
            uint32_t bF[8][2];
            #pragma unroll
            for (int nt = 0; nt < 4; nt++) {
                uint32_t r0, r1, r2, r3;
                uint32_t addr = smem_u32(
                    &Bs[s][wn + nt * 16 + lb_row][ks * 16 + lb_seg * 8]);
                ldmatrix_x4(r0, r1, r2, r3, addr);
                bF[nt * 2 + 0][0] = r0; bF[nt * 2 + 0][1] = r1;
                bF[nt * 2 + 1][0] = r2; bF[nt * 2 + 1][1] = r3;
            }
            #pragma unroll
            for (int mt = 0; mt < 2; mt++)
                #pragma unroll
                for (int nt = 0; nt < 8; nt++)
                    mma_bf16(d[mt][nt][0], d[mt][nt][1], d[mt][nt][2], d[mt][nt][3],
                             aF[mt][0], aF[mt][1], aF[mt][2], aF[mt][3],
                             bF[nt][0], bF[nt][1]);
        }
        __syncthreads();
    }

    // Epilogue: +bias, q14, store.
    // d0,d1 -> (row g,   col 2tq, 2tq+1); d2,d3 -> (row g+8, same cols)
    #pragma unroll
    for (int mt = 0; mt < 2; mt++) {
        int r0 = m0 + wm + mt * 16 + g;
        int r1 = r0 + 8;
        #pragma unroll
        for (int nt = 0; nt < 8; nt++) {
            int cl = wn + nt * 8 + tq * 2;     // col within tile
            float b0 = sb_bias[cl], b1 = sb_bias[cl + 1];
            float2 o0, o1;
            o0.x = qround(d[mt][nt][0] + b0, S14F, I14F);
            o0.y = qround(d[mt][nt][1] + b1, S14F, I14F);
            o1.x = qround(d[mt][nt][2] + b0, S14F, I14F);
            o1.y = qround(d[mt][nt][3] + b1, S14F, I14F);
            *reinterpret_cast<float2*>(C + (size_t)r0 * N_DIM + n0 + cl) = o0;
            *reinterpret_cast<float2*>(C + (size_t)r1 * N_DIM + n0 + cl) = o1;
        }
    }
}

// ---------------------------------------------------------------------------
// Fused gate epilogue over [B, H], float4-vectorized.
// ---------------------------------------------------------------------------
__global__ __launch_bounds__(256)
void qgru_epilogue(const float* __restrict__ hidden, float* __restrict__ out)
{
    int idx = blockIdx.x * blockDim.x + threadIdx.x;
    if (idx >= (M_DIM * H_DIM) / 4) return;
    int b = idx >> 7;
    int h = (idx & 127) << 2;

    const float* gib = g_gi + (size_t)b * N_DIM;
    const float* ghb = g_gh + (size_t)b * N_DIM;

    float4 ir = *reinterpret_cast<const float4*>(gib + h);
    float4 ii = *reinterpret_cast<const float4*>(gib + h + H_DIM);
    float4 in_ = *reinterpret_cast<const float4*>(gib + h + 2 * H_DIM);
    float4 hr = *reinterpret_cast<const float4*>(ghb + h);
    float4 hi = *reinterpret_cast<const float4*>(ghb + h + H_DIM);
    float4 hn = *reinterpret_cast<const float4*>(ghb + h + 2 * H_DIM);
    float4 hd = *reinterpret_cast<const float4*>(hidden + (size_t)b * H_DIM + h);

    float irA[4] = {ir.x, ir.y, ir.z, ir.w};
    float iiA[4] = {ii.x, ii.y, ii.z, ii.w};
    float inA[4] = {in_.x, in_.y, in_.z, in_.w};
    float hrA[4] = {hr.x, hr.y, hr.z, hr.w};
    float hiA[4] = {hi.x, hi.y, hi.z, hi.w};
    float hnA[4] = {hn.x, hn.y, hn.z, hn.w};
    float hdA[4] = {hd.x, hd.y, hd.z, hd.w};
    float res[4];

    #pragma unroll
    for (int l = 0; l < 4; l++) {
        float rg  = qsig(__fadd_rn(irA[l], hrA[l]));
        float ig  = qsig(__fadd_rn(iiA[l], hiA[l]));
        float hnq = qround(hnA[l], Q27F, IQ27F);
        float rh  = qround(__fmul_rn(rg, hnq), S15F, I15F);
        float ng  = qtanhf_(__fadd_rn(rh, inA[l]));
        float nh  = qround(hdA[l], S15F, I15F);
        res[l] = __fadd_rn(ng, __fmul_rn(ig, __fsub_rn(nh, ng)));
    }

    float4 o = {res[0], res[1], res[2], res[3]};
    *reinterpret_cast<float4*>(out + (size_t)b * H_DIM + h) = o;
}

// ---------------------------------------------------------------------------
extern "C" void kernel_launch(void* const* d_in, const int* in_sizes, int n_in,
                              void* d_out, int out_size)
{
    const float* x   = (const float*)d_in[0];
    const float* h   = (const float*)d_in[1];
    const float* wih = (const float*)d_in[2];
    const float* whh = (const float*)d_in[3];
    const float* bih = (const float*)d_in[4];
    const float* bhh = (const float*)d_in[5];
    float* out = (float*)d_out;

    __nv_bfloat16 *xp, *hp, *wip, *whp;
    cudaGetSymbolAddress((void**)&xp,  g_xp);
    cudaGetSymbolAddress((void**)&hp,  g_hp);
    cudaGetSymbolAddress((void**)&wip, g_wip);
    cudaGetSymbolAddress((void**)&whp, g_whp);

    const int nA = M_DIM * K_DIM;
    const int nW = N_DIM * K_DIM;
    split_pack<<<(nA + 255) / 256, 256>>>(x,   xp,  M_DIM, 0);
    split_pack<<<(nA + 255) / 256, 256>>>(h,   hp,  M_DIM, 0);
    split_pack<<<(nW + 255) / 256, 256>>>(wih, wip, N_DIM, 1);
    split_pack<<<(nW + 255) / 256, 256>>>(whh, whp, N_DIM, 1);

    dim3 grid(N_DIM / TILE_N, M_DIM / TILE_M, 2);   // (12, 64, 2)
    gemm_mma<<<grid, 256>>>(bih, bhh);

    int total = (M_DIM * H_DIM) / 4;
    qgru_epilogue<<<(total + 255) / 256, 256>>>(h, out);
}